// round 1
// baseline (speedup 1.0000x reference)
#include <cuda_runtime.h>
#include <math.h>

// Problem constants
#define HDIM 128
#define FDIM 64
#define THDIM 384              // 3*H
#define IS3  0.5773502691896258f      // 1/sqrt(3)
#define ISH  0.08838834764831845f     // 1/sqrt(128)
#define SSC  1.6666666666666667f      // 1/0.6

#define MAXN 50000
#define MAXE 400000

// Scratch (device globals: allocation-free)
__device__ float g_xd  [MAXN * THDIM];        // x_defect @ W_defect + b      (76.8 MB)
__device__ float g_h1  [MAXN * FDIM];         // ScaledSiLU(x @ W_x1 + b)     (12.8 MB)
__device__ float g_xh  [MAXN * THDIM];        // h1 @ W_x2 + b                (76.8 MB)
__device__ float g_rbf [(size_t)MAXE * THDIM];// edge_feat @ W_edge + b       (614 MB)
__device__ float g_lvec[MAXN * 3 * HDIM];     // d_vec_raw @ W_lvec           (76.8 MB)

// ---------------------------------------------------------------------------
// Zero-fill d_out (accumulators live there)
// ---------------------------------------------------------------------------
__global__ void zero_kernel(float4* __restrict__ p, long n4) {
    long i = (long)blockIdx.x * blockDim.x + threadIdx.x;
    if (i < n4) p[i] = make_float4(0.f, 0.f, 0.f, 0.f);
}

// ---------------------------------------------------------------------------
// Generic fp32 SGEMM: C[M,N] = act(A[M,K] @ W[K,N] + bias)
// Register-tiled TM x TN, As stored transposed for vectorized reads.
// ACT: 0 = none, 1 = ScaledSiLU.  HASB: bias present.
// ---------------------------------------------------------------------------
template<int BM, int BN, int BK, int TM, int TN, int ACT, int HASB>
__global__ void __launch_bounds__(256)
sgemm_kernel(const float* __restrict__ A, const float* __restrict__ W,
             const float* __restrict__ bias, float* __restrict__ C,
             int M, int N, int K)
{
    __shared__ float As[BK][BM];
    __shared__ float Ws[BK][BN];

    const int tid  = threadIdx.x;
    const int row0 = blockIdx.x * BM;
    const int col0 = blockIdx.y * BN;
    const int tx   = tid % (BN / TN);
    const int ty   = tid / (BN / TN);

    const int aRow = tid / (BK / 4);
    const int aCol = (tid % (BK / 4)) * 4;
    const int wRow = tid / (BN / 4);
    const int wCol = (tid % (BN / 4)) * 4;

    float acc[TM][TN];
#pragma unroll
    for (int i = 0; i < TM; i++)
#pragma unroll
        for (int j = 0; j < TN; j++) acc[i][j] = 0.f;

    for (int k0 = 0; k0 < K; k0 += BK) {
        // load A tile (transposed into As[k][m]) with row guard
#pragma unroll
        for (int r = 0; r < BM; r += 256 / (BK / 4)) {
            int gr = row0 + aRow + r;
            float4 v = make_float4(0.f, 0.f, 0.f, 0.f);
            if (gr < M)
                v = *(const float4*)(A + (size_t)gr * K + k0 + aCol);
            As[aCol + 0][aRow + r] = v.x;
            As[aCol + 1][aRow + r] = v.y;
            As[aCol + 2][aRow + r] = v.z;
            As[aCol + 3][aRow + r] = v.w;
        }
        // load W tile
#pragma unroll
        for (int r = 0; r < BK; r += 256 / (BN / 4)) {
            *(float4*)&Ws[wRow + r][wCol] =
                *(const float4*)(W + (size_t)(k0 + wRow + r) * N + col0 + wCol);
        }
        __syncthreads();

#pragma unroll
        for (int k = 0; k < BK; k++) {
            float am[TM], wn[TN];
#pragma unroll
            for (int i = 0; i < TM; i += 4)
                *(float4*)&am[i] = *(const float4*)&As[k][ty * TM + i];
#pragma unroll
            for (int j = 0; j < TN; j += 4)
                *(float4*)&wn[j] = *(const float4*)&Ws[k][tx * TN + j];
#pragma unroll
            for (int i = 0; i < TM; i++)
#pragma unroll
                for (int j = 0; j < TN; j++)
                    acc[i][j] += am[i] * wn[j];
        }
        __syncthreads();
    }

    float bv[TN];
#pragma unroll
    for (int j = 0; j < TN; j++)
        bv[j] = HASB ? bias[col0 + tx * TN + j] : 0.f;

#pragma unroll
    for (int i = 0; i < TM; i++) {
        int gr = row0 + ty * TM + i;
        if (gr >= M) continue;
#pragma unroll
        for (int j = 0; j < TN; j += 4) {
            float t[4];
#pragma unroll
            for (int q = 0; q < 4; q++) {
                float v = acc[i][j + q] + bv[j + q];
                if (ACT == 1) v = v / (1.f + expf(-v)) * SSC;  // ScaledSiLU
                t[q] = v;
            }
            *(float4*)(C + (size_t)gr * N + col0 + tx * TN + j) =
                make_float4(t[0], t[1], t[2], t[3]);
        }
    }
}

// ---------------------------------------------------------------------------
// Vectorized global reduction (sm_90+)
// ---------------------------------------------------------------------------
__device__ __forceinline__ void red4(float* p, float4 v) {
    asm volatile("red.global.add.v4.f32 [%0], {%1,%2,%3,%4};"
                 :: "l"(p), "f"(v.x), "f"(v.y), "f"(v.z), "f"(v.w)
                 : "memory");
}

// ---------------------------------------------------------------------------
// Edge kernel: msg = xh[j]*(xd[j]+xd[i])*rbf/sqrt(3); scatter-add d_x, d_vec
// 32 threads per edge, 4 columns (float4) per thread.
// ---------------------------------------------------------------------------
__global__ void edge_kernel(const float* __restrict__ xh, const float* __restrict__ xd,
                            const float* __restrict__ vec, const float* __restrict__ rbf,
                            const float* __restrict__ ev,
                            const int* __restrict__ ej, const int* __restrict__ ei,
                            float* __restrict__ dx, float* __restrict__ dvec, int E)
{
    long g = (long)blockIdx.x * blockDim.x + threadIdx.x;
    int e = (int)(g >> 5);
    int q = (int)(g & 31);
    if (e >= E) return;

    int j = ej[e];
    int i = ei[e];

    const float4* xhj = (const float4*)(xh + (size_t)j * THDIM);
    const float4* xdj = (const float4*)(xd + (size_t)j * THDIM);
    const float4* xdi = (const float4*)(xd + (size_t)i * THDIM);
    const float4* rb  = (const float4*)(rbf + (size_t)e * THDIM);

    float4 m[3];
#pragma unroll
    for (int c = 0; c < 3; c++) {
        float4 a  = xhj[q + 32 * c];
        float4 b1 = xdj[q + 32 * c];
        float4 b2 = xdi[q + 32 * c];
        float4 r  = rb [q + 32 * c];
        m[c].x = a.x * (b1.x + b2.x) * r.x * IS3;
        m[c].y = a.y * (b1.y + b2.y) * r.y * IS3;
        m[c].z = a.z * (b1.z + b2.z) * r.z * IS3;
        m[c].w = a.w * (b1.w + b2.w) * r.w * IS3;
    }

    float evd[3];
    evd[0] = ev[(size_t)e * 3 + 0];
    evd[1] = ev[(size_t)e * 3 + 1];
    evd[2] = ev[(size_t)e * 3 + 2];

    const float4* vj = (const float4*)(vec + (size_t)j * THDIM);
    float* dvbase = dvec + (size_t)i * THDIM;
    int h0 = q * 4;

#pragma unroll
    for (int d = 0; d < 3; d++) {
        float4 v = vj[d * 32 + q];
        float4 r;
        r.x = (m[0].x * v.x + m[1].x * evd[d]) * ISH;
        r.y = (m[0].y * v.y + m[1].y * evd[d]) * ISH;
        r.z = (m[0].z * v.z + m[1].z * evd[d]) * ISH;
        r.w = (m[0].w * v.w + m[1].w * evd[d]) * ISH;
        red4(dvbase + d * HDIM + h0, r);
    }
    red4(dx + (size_t)i * HDIM + h0, m[2]);
}

// ---------------------------------------------------------------------------
// Vector activation epilogue: gvec = vraw @ W_gvec (reduction),
// dot = sum_d lvec*gvec, masked combine. In-place on dvec (raw -> final).
// ---------------------------------------------------------------------------
__global__ void combine_kernel(const float* __restrict__ lvec,
                               const float* __restrict__ Wg,
                               float* __restrict__ dvec, int Nn)
{
    __shared__ float wg_s[HDIM];
    __shared__ float red_s[4][3];
    int t = threadIdx.x;   // 128
    wg_s[t] = Wg[t];
    __syncthreads();

    for (int n = blockIdx.x; n < Nn; n += gridDim.x) {
        const float* vr = dvec + (size_t)n * THDIM;
        float v0 = vr[t], v1 = vr[HDIM + t], v2 = vr[2 * HDIM + t];
        float w = wg_s[t];
        float p0 = v0 * w, p1 = v1 * w, p2 = v2 * w;
#pragma unroll
        for (int off = 16; off > 0; off >>= 1) {
            p0 += __shfl_xor_sync(0xffffffffu, p0, off);
            p1 += __shfl_xor_sync(0xffffffffu, p1, off);
            p2 += __shfl_xor_sync(0xffffffffu, p2, off);
        }
        if ((t & 31) == 0) {
            red_s[t >> 5][0] = p0;
            red_s[t >> 5][1] = p1;
            red_s[t >> 5][2] = p2;
        }
        __syncthreads();
        float gv0 = red_s[0][0] + red_s[1][0] + red_s[2][0] + red_s[3][0];
        float gv1 = red_s[0][1] + red_s[1][1] + red_s[2][1] + red_s[3][1];
        float gv2 = red_s[0][2] + red_s[1][2] + red_s[2][2] + red_s[3][2];

        const float* lv = lvec + (size_t)n * THDIM;
        float l0 = lv[t], l1 = lv[HDIM + t], l2 = lv[2 * HDIM + t];
        float dot = l0 * gv0 + l1 * gv1 + l2 * gv2;

        float* o = dvec + (size_t)n * THDIM;
        if (dot >= 0.f) {
            o[t] = l0; o[HDIM + t] = l1; o[2 * HDIM + t] = l2;
        } else {
            o[t]            = (l0 + gv0) * 0.5f;
            o[HDIM + t]     = (l1 + gv1) * 0.5f;
            o[2 * HDIM + t] = (l2 + gv2) * 0.5f;
        }
        __syncthreads();   // protect red_s for next iteration
    }
}

// ---------------------------------------------------------------------------
// Launch
// ---------------------------------------------------------------------------
extern "C" void kernel_launch(void* const* d_in, const int* in_sizes, int n_in,
                              void* d_out, int out_size)
{
    const float* x     = (const float*)d_in[0];
    const float* xdef  = (const float*)d_in[1];
    const float* vec   = (const float*)d_in[2];
    const float* efeat = (const float*)d_in[3];
    const float* evec  = (const float*)d_in[4];
    const int*   eidx  = (const int*)  d_in[5];
    const float* Wd    = (const float*)d_in[6];
    const float* bd    = (const float*)d_in[7];
    const float* W1    = (const float*)d_in[8];
    const float* b1    = (const float*)d_in[9];
    const float* W2    = (const float*)d_in[10];
    const float* b2    = (const float*)d_in[11];
    const float* We    = (const float*)d_in[12];
    const float* be    = (const float*)d_in[13];
    const float* Wl    = (const float*)d_in[14];
    const float* Wg    = (const float*)d_in[15];

    int N = in_sizes[0] / HDIM;     // 50000
    int E = in_sizes[4] / 3;        // 400000

    float *p_xd, *p_h1, *p_xh, *p_rbf, *p_lvec;
    cudaGetSymbolAddress((void**)&p_xd,   g_xd);
    cudaGetSymbolAddress((void**)&p_h1,   g_h1);
    cudaGetSymbolAddress((void**)&p_xh,   g_xh);
    cudaGetSymbolAddress((void**)&p_rbf,  g_rbf);
    cudaGetSymbolAddress((void**)&p_lvec, g_lvec);

    float* dx   = (float*)d_out;                     // [N,128]
    float* dvec = (float*)d_out + (size_t)N * HDIM;  // [N,3,128]

    // 0) zero accumulators in d_out
    long n4 = (long)out_size / 4;
    zero_kernel<<<(unsigned)((n4 + 255) / 256), 256>>>((float4*)d_out, n4);

    dim3 gN((N + 127) / 128, 3);
    dim3 gN1((N + 127) / 128, 1);
    dim3 gE((E + 127) / 128, 3);
    dim3 gL((3 * N + 127) / 128, 1);

    // 1) xd = x_defect @ W_defect + b_defect            [N,384], K=128
    sgemm_kernel<128,128,16,8,8,0,1><<<gN, 256>>>(xdef, Wd, bd, p_xd, N, THDIM, HDIM);
    // 2) h1 = ScaledSiLU(x @ W_x1 + b_x1)               [N,64],  K=128
    sgemm_kernel<128, 64,16,8,4,1,1><<<gN1,256>>>(x, W1, b1, p_h1, N, FDIM, HDIM);
    // 3) xh = h1 @ W_x2 + b_x2                          [N,384], K=64
    sgemm_kernel<128,128,16,8,8,0,1><<<gN, 256>>>(p_h1, W2, b2, p_xh, N, THDIM, FDIM);
    // 4) rbf = edge_feat @ W_edge + b_edge              [E,384], K=64
    sgemm_kernel<128,128,16,8,8,0,1><<<gE, 256>>>(efeat, We, be, p_rbf, E, THDIM, FDIM);

    // 5) edge message + scatter-add into d_out
    long tot = (long)E * 32;
    edge_kernel<<<(unsigned)((tot + 255) / 256), 256>>>(
        p_xh, p_xd, vec, p_rbf, evec, eidx, eidx + E, dx, dvec, E);

    // 6) lvec = d_vec_raw @ W_lvec  (no bias)           [3N,128], K=128
    sgemm_kernel<128,128,16,8,8,0,0><<<gL, 256>>>(dvec, Wl, nullptr, p_lvec, 3 * N, HDIM, HDIM);

    // 7) vector activation epilogue (in-place on dvec region of d_out)
    combine_kernel<<<2048, 128>>>(p_lvec, Wg, dvec, N);
}

// round 2
// speedup vs baseline: 1.3531x; 1.3531x over previous
#include <cuda_runtime.h>
#include <math.h>

// Problem constants
#define HDIM 128
#define FDIM 64
#define THDIM 384              // 3*H
#define IS3  0.5773502691896258f      // 1/sqrt(3)
#define ISH  0.08838834764831845f     // 1/sqrt(128)
#define SSC  1.6666666666666667f      // 1/0.6

#define MAXN 50000
#define MAXE 400000

typedef unsigned long long ull;

// Scratch (device globals: allocation-free)
__device__ float g_xd  [MAXN * THDIM];        // x_defect @ W_defect + b
__device__ float g_h1  [MAXN * FDIM];         // ScaledSiLU(x @ W_x1 + b)
__device__ float g_xh  [MAXN * THDIM];        // h1 @ W_x2 + b
__device__ float g_lvec[MAXN * 3 * HDIM];     // d_vec_raw @ W_lvec

// ---------------------------------------------------------------------------
// Packed fp32x2 helpers (Blackwell FFMA2 path — ptxas never auto-fuses)
// ---------------------------------------------------------------------------
__device__ __forceinline__ ull pk(float lo, float hi) {
    ull r; asm("mov.b64 %0, {%1, %2};" : "=l"(r) : "f"(lo), "f"(hi)); return r;
}
__device__ __forceinline__ void upk(ull v, float& lo, float& hi) {
    asm("mov.b64 {%0, %1}, %2;" : "=f"(lo), "=f"(hi) : "l"(v));
}
__device__ __forceinline__ void fma2(ull& d, ull a, ull b) {
    asm("fma.rn.f32x2 %0, %1, %2, %0;" : "+l"(d) : "l"(a), "l"(b));
}

// ---------------------------------------------------------------------------
// Zero-fill d_out (accumulators live there)
// ---------------------------------------------------------------------------
__global__ void zero_kernel(float4* __restrict__ p, long n4) {
    long i = (long)blockIdx.x * blockDim.x + threadIdx.x;
    if (i < n4) p[i] = make_float4(0.f, 0.f, 0.f, 0.f);
}

// ---------------------------------------------------------------------------
// fp32 SGEMM with FFMA2 inner product: C = act(A @ W + bias)
// ---------------------------------------------------------------------------
template<int BM, int BN, int BK, int TM, int TN, int ACT, int HASB>
__global__ void __launch_bounds__(256)
sgemm_kernel(const float* __restrict__ A, const float* __restrict__ W,
             const float* __restrict__ bias, float* __restrict__ C,
             int M, int N, int K)
{
    __shared__ float As[BK][BM];
    __shared__ float Ws[BK][BN];

    const int tid  = threadIdx.x;
    const int row0 = blockIdx.x * BM;
    const int col0 = blockIdx.y * BN;
    const int tx   = tid % (BN / TN);
    const int ty   = tid / (BN / TN);

    const int aRow = tid / (BK / 4);
    const int aCol = (tid % (BK / 4)) * 4;
    const int wRow = tid / (BN / 4);
    const int wCol = (tid % (BN / 4)) * 4;

    ull acc2[TM][TN / 2];
#pragma unroll
    for (int i = 0; i < TM; i++)
#pragma unroll
        for (int j = 0; j < TN / 2; j++) acc2[i][j] = 0ULL;

    for (int k0 = 0; k0 < K; k0 += BK) {
#pragma unroll
        for (int r = 0; r < BM; r += 256 / (BK / 4)) {
            int gr = row0 + aRow + r;
            float4 v = make_float4(0.f, 0.f, 0.f, 0.f);
            if (gr < M)
                v = *(const float4*)(A + (size_t)gr * K + k0 + aCol);
            As[aCol + 0][aRow + r] = v.x;
            As[aCol + 1][aRow + r] = v.y;
            As[aCol + 2][aRow + r] = v.z;
            As[aCol + 3][aRow + r] = v.w;
        }
#pragma unroll
        for (int r = 0; r < BK; r += 256 / (BN / 4)) {
            *(float4*)&Ws[wRow + r][wCol] =
                *(const float4*)(W + (size_t)(k0 + wRow + r) * N + col0 + wCol);
        }
        __syncthreads();

#pragma unroll
        for (int k = 0; k < BK; k++) {
            float am[TM], wn[TN];
#pragma unroll
            for (int i = 0; i < TM; i += 4)
                *(float4*)&am[i] = *(const float4*)&As[k][ty * TM + i];
#pragma unroll
            for (int j = 0; j < TN; j += 4)
                *(float4*)&wn[j] = *(const float4*)&Ws[k][tx * TN + j];
            ull wn2[TN / 2];
#pragma unroll
            for (int j = 0; j < TN / 2; j++) wn2[j] = pk(wn[2 * j], wn[2 * j + 1]);
#pragma unroll
            for (int i = 0; i < TM; i++) {
                ull a2 = pk(am[i], am[i]);
#pragma unroll
                for (int j = 0; j < TN / 2; j++)
                    fma2(acc2[i][j], a2, wn2[j]);
            }
        }
        __syncthreads();
    }

    float bv[TN];
#pragma unroll
    for (int j = 0; j < TN; j++)
        bv[j] = HASB ? bias[col0 + tx * TN + j] : 0.f;

#pragma unroll
    for (int i = 0; i < TM; i++) {
        int gr = row0 + ty * TM + i;
        if (gr >= M) continue;
#pragma unroll
        for (int j = 0; j < TN; j += 4) {
            float t[4];
            upk(acc2[i][j / 2],     t[0], t[1]);
            upk(acc2[i][j / 2 + 1], t[2], t[3]);
#pragma unroll
            for (int q = 0; q < 4; q++) {
                float v = t[q] + bv[j + q];
                if (ACT == 1) v = v / (1.f + expf(-v)) * SSC;  // ScaledSiLU
                t[q] = v;
            }
            *(float4*)(C + (size_t)gr * N + col0 + tx * TN + j) =
                make_float4(t[0], t[1], t[2], t[3]);
        }
    }
}

// ---------------------------------------------------------------------------
// Vectorized global reduction
// ---------------------------------------------------------------------------
__device__ __forceinline__ void red4(float* p, float4 v) {
    asm volatile("red.global.add.v4.f32 [%0], {%1,%2,%3,%4};"
                 :: "l"(p), "f"(v.x), "f"(v.y), "f"(v.z), "f"(v.w)
                 : "memory");
}

// ---------------------------------------------------------------------------
// Fused edge kernel: rbf = ef @ We + be computed in-register from smem W,
// then msg = xh[j]*(xd[j]+xd[i])*rbf/sqrt(3); scatter-add d_x, d_vec.
// One warp processes EB=4 edges at a time (W smem read amortized 4x).
// Lane q owns cols {4q..4q+3} of each 128-col role block.
// ---------------------------------------------------------------------------
#define EB 4
__global__ void __launch_bounds__(256, 2)
edge_fused_kernel(const float* __restrict__ xh, const float* __restrict__ xd,
                  const float* __restrict__ vec, const float* __restrict__ efeat,
                  const float* __restrict__ We, const float* __restrict__ be,
                  const float* __restrict__ ev,
                  const int* __restrict__ ej, const int* __restrict__ ei,
                  float* __restrict__ dx, float* __restrict__ dvec, int E)
{
    extern __shared__ float smem[];
    float* Ws = smem;                         // [64][384]
    float* efs = smem + 64 * THDIM;           // [8 warps][EB][64]

    const int tid = threadIdx.x;

    // cooperative load of W_edge into smem (24576 floats)
    for (int idx = tid; idx < 64 * THDIM / 4; idx += 256)
        ((float4*)Ws)[idx] = ((const float4*)We)[idx];
    __syncthreads();

    const int warp = tid >> 5;
    const int q    = tid & 31;
    float* myef = efs + warp * (EB * 64);

    // bias (per-lane columns), loaded once
    const float4 be0 = *(const float4*)(be + 4 * q);
    const float4 be1 = *(const float4*)(be + HDIM + 4 * q);
    const float4 be2 = *(const float4*)(be + 2 * HDIM + 4 * q);

    const int G = (E + EB - 1) / EB;
    const int stride = gridDim.x * 8;

    for (int g = blockIdx.x * 8 + warp; g < G; g += stride) {
        const int e0 = g * EB;

        // stage edge_feat rows for this group
        for (int idx = q; idx < EB * 64; idx += 32) {
            int e = idx >> 6, k = idx & 63;
            myef[idx] = (e0 + e < E) ? efeat[(size_t)(e0 + e) * FDIM + k] : 0.f;
        }
        __syncwarp();

        // rbf accumulation: acc[e][c6], c6 = 2*c + half, packed col pairs
        ull acc[EB][6];
#pragma unroll
        for (int e = 0; e < EB; e++)
#pragma unroll
            for (int c = 0; c < 6; c++) acc[e][c] = 0ULL;

#pragma unroll 8
        for (int k = 0; k < 64; k++) {
            const float4* wr = (const float4*)(Ws + k * THDIM);
            float4 w0 = wr[q];
            float4 w1 = wr[32 + q];
            float4 w2 = wr[64 + q];
            ull wp[6];
            wp[0] = pk(w0.x, w0.y); wp[1] = pk(w0.z, w0.w);
            wp[2] = pk(w1.x, w1.y); wp[3] = pk(w1.z, w1.w);
            wp[4] = pk(w2.x, w2.y); wp[5] = pk(w2.z, w2.w);
#pragma unroll
            for (int e = 0; e < EB; e++) {
                float efv = myef[e * 64 + k];     // broadcast LDS
                ull ef2 = pk(efv, efv);
#pragma unroll
                for (int c = 0; c < 6; c++) fma2(acc[e][c], ef2, wp[c]);
            }
        }

        // epilogue per edge
#pragma unroll
        for (int e = 0; e < EB; e++) {
            int eg = e0 + e;
            if (eg >= E) break;
            int j = ej[eg];
            int i = ei[eg];

            float r0[4], r1[4], r2[4];
            upk(acc[e][0], r0[0], r0[1]); upk(acc[e][1], r0[2], r0[3]);
            upk(acc[e][2], r1[0], r1[1]); upk(acc[e][3], r1[2], r1[3]);
            upk(acc[e][4], r2[0], r2[1]); upk(acc[e][5], r2[2], r2[3]);
            r0[0] += be0.x; r0[1] += be0.y; r0[2] += be0.z; r0[3] += be0.w;
            r1[0] += be1.x; r1[1] += be1.y; r1[2] += be1.z; r1[3] += be1.w;
            r2[0] += be2.x; r2[1] += be2.y; r2[2] += be2.z; r2[3] += be2.w;

            const float4* xhj = (const float4*)(xh + (size_t)j * THDIM);
            const float4* xdj = (const float4*)(xd + (size_t)j * THDIM);
            const float4* xdi = (const float4*)(xd + (size_t)i * THDIM);

            float4 m0, m1, m2;
            {
                float4 a = xhj[q],      b1 = xdj[q],      b2 = xdi[q];
                m0.x = a.x * (b1.x + b2.x) * r0[0] * IS3;
                m0.y = a.y * (b1.y + b2.y) * r0[1] * IS3;
                m0.z = a.z * (b1.z + b2.z) * r0[2] * IS3;
                m0.w = a.w * (b1.w + b2.w) * r0[3] * IS3;
            }
            {
                float4 a = xhj[32 + q], b1 = xdj[32 + q], b2 = xdi[32 + q];
                m1.x = a.x * (b1.x + b2.x) * r1[0] * IS3;
                m1.y = a.y * (b1.y + b2.y) * r1[1] * IS3;
                m1.z = a.z * (b1.z + b2.z) * r1[2] * IS3;
                m1.w = a.w * (b1.w + b2.w) * r1[3] * IS3;
            }
            {
                float4 a = xhj[64 + q], b1 = xdj[64 + q], b2 = xdi[64 + q];
                m2.x = a.x * (b1.x + b2.x) * r2[0] * IS3;
                m2.y = a.y * (b1.y + b2.y) * r2[1] * IS3;
                m2.z = a.z * (b1.z + b2.z) * r2[2] * IS3;
                m2.w = a.w * (b1.w + b2.w) * r2[3] * IS3;
            }

            float evd[3];
            evd[0] = ev[(size_t)eg * 3 + 0];
            evd[1] = ev[(size_t)eg * 3 + 1];
            evd[2] = ev[(size_t)eg * 3 + 2];

            const float4* vj = (const float4*)(vec + (size_t)j * THDIM);
            float* dvbase = dvec + (size_t)i * THDIM;
            int h0 = q * 4;

#pragma unroll
            for (int d = 0; d < 3; d++) {
                float4 v = vj[d * 32 + q];
                float4 r;
                r.x = (m0.x * v.x + m1.x * evd[d]) * ISH;
                r.y = (m0.y * v.y + m1.y * evd[d]) * ISH;
                r.z = (m0.z * v.z + m1.z * evd[d]) * ISH;
                r.w = (m0.w * v.w + m1.w * evd[d]) * ISH;
                red4(dvbase + d * HDIM + h0, r);
            }
            red4(dx + (size_t)i * HDIM + h0, m2);
        }
        __syncwarp();
    }
}

// ---------------------------------------------------------------------------
// Vector activation epilogue
// ---------------------------------------------------------------------------
__global__ void combine_kernel(const float* __restrict__ lvec,
                               const float* __restrict__ Wg,
                               float* __restrict__ dvec, int Nn)
{
    __shared__ float wg_s[HDIM];
    __shared__ float red_s[4][3];
    int t = threadIdx.x;   // 128
    wg_s[t] = Wg[t];
    __syncthreads();

    for (int n = blockIdx.x; n < Nn; n += gridDim.x) {
        const float* vr = dvec + (size_t)n * THDIM;
        float v0 = vr[t], v1 = vr[HDIM + t], v2 = vr[2 * HDIM + t];
        float w = wg_s[t];
        float p0 = v0 * w, p1 = v1 * w, p2 = v2 * w;
#pragma unroll
        for (int off = 16; off > 0; off >>= 1) {
            p0 += __shfl_xor_sync(0xffffffffu, p0, off);
            p1 += __shfl_xor_sync(0xffffffffu, p1, off);
            p2 += __shfl_xor_sync(0xffffffffu, p2, off);
        }
        if ((t & 31) == 0) {
            red_s[t >> 5][0] = p0;
            red_s[t >> 5][1] = p1;
            red_s[t >> 5][2] = p2;
        }
        __syncthreads();
        float gv0 = red_s[0][0] + red_s[1][0] + red_s[2][0] + red_s[3][0];
        float gv1 = red_s[0][1] + red_s[1][1] + red_s[2][1] + red_s[3][1];
        float gv2 = red_s[0][2] + red_s[1][2] + red_s[2][2] + red_s[3][2];

        const float* lv = lvec + (size_t)n * THDIM;
        float l0 = lv[t], l1 = lv[HDIM + t], l2 = lv[2 * HDIM + t];
        float dot = l0 * gv0 + l1 * gv1 + l2 * gv2;

        float* o = dvec + (size_t)n * THDIM;
        if (dot >= 0.f) {
            o[t] = l0; o[HDIM + t] = l1; o[2 * HDIM + t] = l2;
        } else {
            o[t]            = (l0 + gv0) * 0.5f;
            o[HDIM + t]     = (l1 + gv1) * 0.5f;
            o[2 * HDIM + t] = (l2 + gv2) * 0.5f;
        }
        __syncthreads();
    }
}

// ---------------------------------------------------------------------------
// Launch
// ---------------------------------------------------------------------------
extern "C" void kernel_launch(void* const* d_in, const int* in_sizes, int n_in,
                              void* d_out, int out_size)
{
    const float* x     = (const float*)d_in[0];
    const float* xdef  = (const float*)d_in[1];
    const float* vec   = (const float*)d_in[2];
    const float* efeat = (const float*)d_in[3];
    const float* evec  = (const float*)d_in[4];
    const int*   eidx  = (const int*)  d_in[5];
    const float* Wd    = (const float*)d_in[6];
    const float* bd    = (const float*)d_in[7];
    const float* W1    = (const float*)d_in[8];
    const float* b1    = (const float*)d_in[9];
    const float* W2    = (const float*)d_in[10];
    const float* b2    = (const float*)d_in[11];
    const float* We    = (const float*)d_in[12];
    const float* be    = (const float*)d_in[13];
    const float* Wl    = (const float*)d_in[14];
    const float* Wg    = (const float*)d_in[15];

    int N = in_sizes[0] / HDIM;     // 50000
    int E = in_sizes[4] / 3;        // 400000

    float *p_xd, *p_h1, *p_xh, *p_lvec;
    cudaGetSymbolAddress((void**)&p_xd,   g_xd);
    cudaGetSymbolAddress((void**)&p_h1,   g_h1);
    cudaGetSymbolAddress((void**)&p_xh,   g_xh);
    cudaGetSymbolAddress((void**)&p_lvec, g_lvec);

    float* dx   = (float*)d_out;                     // [N,128]
    float* dvec = (float*)d_out + (size_t)N * HDIM;  // [N,3,128]

    // 0) zero accumulators in d_out
    long n4 = (long)out_size / 4;
    zero_kernel<<<(unsigned)((n4 + 255) / 256), 256>>>((float4*)d_out, n4);

    dim3 gN((N + 127) / 128, 3);
    dim3 gN1((N + 127) / 128, 1);
    dim3 gL((3 * N + 127) / 128, 1);

    // 1) xd = x_defect @ W_defect + b                   [N,384], K=128
    sgemm_kernel<128,128,16,8,8,0,1><<<gN, 256>>>(xdef, Wd, bd, p_xd, N, THDIM, HDIM);
    // 2) h1 = ScaledSiLU(x @ W_x1 + b)                  [N,64],  K=128
    sgemm_kernel<128, 64,16,8,4,1,1><<<gN1,256>>>(x, W1, b1, p_h1, N, FDIM, HDIM);
    // 3) xh = h1 @ W_x2 + b                             [N,384], K=64
    sgemm_kernel<128,128,16,8,8,0,1><<<gN, 256>>>(p_h1, W2, b2, p_xh, N, THDIM, FDIM);

    // 4) fused: rbf GEMM + edge message + scatter-add
    int smem_bytes = (64 * THDIM + 8 * EB * 64) * 4;   // 104 KB
    cudaFuncSetAttribute(edge_fused_kernel,
                         cudaFuncAttributeMaxDynamicSharedMemorySize, smem_bytes);
    edge_fused_kernel<<<296, 256, smem_bytes>>>(
        p_xh, p_xd, vec, efeat, We, be, evec, eidx, eidx + E, dx, dvec, E);

    // 5) lvec = d_vec_raw @ W_lvec                      [3N,128], K=128
    sgemm_kernel<128,128,16,8,8,0,0><<<gL, 256>>>(dvec, Wl, nullptr, p_lvec, 3 * N, HDIM, HDIM);

    // 6) vector activation epilogue (in-place on dvec region of d_out)
    combine_kernel<<<2048, 128>>>(p_lvec, Wg, dvec, N);
}